// round 10
// baseline (speedup 1.0000x reference)
#include <cuda_runtime.h>

// ---------------------------------------------------------------------------
// Fully fused. Prologue (per block): shuffle-simulate U (16x16), M = Re(U^dag
// Z0 U), sparse-project to 81 multilinear K coefficients as 27 float4 entries
// {K[..,t3=0],K[..,t3=1],K[..,t3=2],pad}. Main: persistent grid-stride over a
// PADDED strip space (4096 strips/plane, shifts-only decode, no int division).
// K-group loop hoisted outside the pixel loop: 27 LDS.128 per 4-pixel strip.
// ---------------------------------------------------------------------------
__global__ void __launch_bounds__(256)
qcl_fused_kernel(const float* __restrict__ x, const float* __restrict__ w,
                 float* __restrict__ out, int nVirt) {
    __shared__ float sUr[16][17];
    __shared__ float sUi[16][17];
    __shared__ float sM[16][17];
    __shared__ float sgc[24], sgs[24];
    __shared__ __align__(16) float sKe[27][4];   // {k(t3=0),k(t3=1),k(t3=2),pad}

    const int tid = threadIdx.x;

    // ---- weights' half-angle sincos (precise) ----
    if (tid < 24) {
        sgc[tid] = cosf(w[tid] * 0.5f);
        sgs[tid] = sinf(w[tid] * 0.5f);
    }
    __syncthreads();

    // ---- shuffle simulator: thread owns amplitude kk of column col ----
    {
        const int lane = tid & 31;
        const int kk   = lane & 15;
        const int col  = ((tid >> 5) << 1) | (lane >> 4);

        float ar = (kk == col) ? 1.f : 0.f;
        float ai = 0.f;

        auto rot = [&](int m, float g00r, float g00i, float g01r, float g01i,
                              float g10r, float g10i, float g11r, float g11i) {
            float pr = __shfl_xor_sync(0xffffffffu, ar, m);
            float pi = __shfl_xor_sync(0xffffffffu, ai, m);
            bool  b  = (kk & m) != 0;
            float ur = b ? pr : ar, ui = b ? pi : ai;
            float wr = b ? ar : pr, wi = b ? ai : pi;
            float c0r = b ? g10r : g00r, c0i = b ? g10i : g00i;
            float c1r = b ? g11r : g01r, c1i = b ? g11i : g01i;
            ar = c0r * ur - c0i * ui + c1r * wr - c1i * wi;
            ai = c0r * ui + c0i * ur + c1r * wi + c1i * wr;
        };
        auto cnot = [&](int mc, int mt) {
            float pr = __shfl_xor_sync(0xffffffffu, ar, mt);
            float pi = __shfl_xor_sync(0xffffffffu, ai, mt);
            if (kk & mc) { ar = pr; ai = pi; }
        };

        #pragma unroll
        for (int g8 = 0; g8 < 8; g8++) {     // layer*4 + q
            int q = g8 & 3;
            int m = 8 >> q;
            int base = g8 * 3;
            float c, s;
            c = sgc[base + 0]; s = sgs[base + 0];          // RX: [[c,-is],[-is,c]]
            rot(m, c, 0.f, 0.f, -s, 0.f, -s, c, 0.f);
            c = sgc[base + 1]; s = sgs[base + 1];          // RY: [[c,-s],[s,c]]
            rot(m, c, 0.f, -s, 0.f, s, 0.f, c, 0.f);
            c = sgc[base + 2]; s = sgs[base + 2];          // RZ: diag(e^-it/2,e^it/2)
            rot(m, c, -s, 0.f, 0.f, 0.f, 0.f, c, s);
            if (q == 3) { cnot(8, 4); cnot(2, 1); cnot(8, 2); cnot(4, 1); }
        }

        sUr[kk][col] = ar;
        sUi[kk][col] = ai;
    }
    __syncthreads();

    // ---- M[i][j] = Re(sum_k z_k conj(U[k][i]) U[k][j]), z_k = (k&8)?-1:+1 ----
    {
        int i = tid >> 4, j = tid & 15;
        float acc = 0.f;
        #pragma unroll
        for (int k = 0; k < 16; k++) {
            float z = (k & 8) ? -1.f : 1.f;
            acc += z * (sUr[k][i] * sUr[k][j] + sUi[k][i] * sUi[k][j]);
        }
        sM[i][j] = acc;
    }
    __syncthreads();

    // ---- sparse projection ----
    // K[t] = (1/16) sum_c (-1)^popc(c & smask) * M[c][c ^ xmask]
    if (tid < 81) {
        int t3 = tid % 3, r = tid / 3;
        int t2 = r % 3;  r /= 3;
        int t1 = r % 3;
        int t0 = r / 3;
        int xmask = ((t0 == 2) << 3) | ((t1 == 2) << 2) | ((t2 == 2) << 1) | (t3 == 2);
        int smask = ((t0 == 1) << 3) | ((t1 == 1) << 2) | ((t2 == 1) << 1) | (t3 == 1);
        float acc = 0.f;
        #pragma unroll
        for (int c = 0; c < 16; c++) {
            float sgn = (__popc(c & smask) & 1) ? -1.f : 1.f;
            acc += sgn * sM[c][c ^ xmask];
        }
        sKe[(t0 * 3 + t1) * 3 + t2][t3] = acc * 0.0625f;
    }
    if (tid >= 81 && tid < 108) sKe[tid - 81][3] = 0.f;   // pad lanes
    __syncthreads();

    const float4* sKe4 = (const float4*)sKe;

    // ---- main phase: persistent grid-stride over PADDED strip ids ----
    // virtual layout: plane = sid>>12 (4096 slots), h = (sid&4095)>>5 (valid <127),
    // w0 = (sid&31)<<2. 32 strips/row, last strip covers 3 pixels.
    const int stride = gridDim.x * blockDim.x;
    for (int sid = blockIdx.x * blockDim.x + tid; sid < nVirt; sid += stride) {
        int p   = sid >> 12;
        int rem = sid & 4095;
        int h   = rem >> 5;
        if (h >= 127) continue;
        int w0  = (rem & 31) << 2;        // 0..124, 16B-aligned
        bool full = (w0 < 124);

        const float* r0 = x + p * 16384 + h * 128 + w0;
        float4 t4 = *(const float4*)r0;
        float4 b4 = *(const float4*)(r0 + 128);
        float  t5 = full ? __ldg(r0 + 4)   : 0.f;
        float  b5 = full ? __ldg(r0 + 132) : 0.f;

        // 5 top + 5 bottom sincos shared across the 4 pixels
        float Ct[5], St[5], Cb[5], Sb[5];
        __sincosf(t4.x, &St[0], &Ct[0]);  __sincosf(b4.x, &Sb[0], &Cb[0]);
        __sincosf(t4.y, &St[1], &Ct[1]);  __sincosf(b4.y, &Sb[1], &Cb[1]);
        __sincosf(t4.z, &St[2], &Ct[2]);  __sincosf(b4.z, &Sb[2], &Cb[2]);
        __sincosf(t4.w, &St[3], &Ct[3]);  __sincosf(b4.w, &Sb[3], &Cb[3]);
        __sincosf(t5,   &St[4], &Ct[4]);  __sincosf(b5,   &Sb[4], &Cb[4]);

        // contraction with K loads hoisted: each K triple loaded ONCE per strip.
        // pixel px wires: 0=Ct/St[px], 1=Ct/St[px+1], 2=Cb/Sb[px], 3=Cb/Sb[px+1]
        float accA[4];
        #pragma unroll
        for (int a = 0; a < 3; a++) {
            float accB[4];
            #pragma unroll
            for (int b = 0; b < 3; b++) {
                const int e = (a * 3 + b) * 3;
                float4 k0 = sKe4[e + 0];
                float4 k1 = sKe4[e + 1];
                float4 k2 = sKe4[e + 2];
                #pragma unroll
                for (int px = 0; px < 4; px++) {
                    float C3 = Cb[px + 1], S3 = Sb[px + 1];
                    float t0v = fmaf(k0.y, C3, fmaf(k0.z, S3, k0.x));
                    float t1v = fmaf(k1.y, C3, fmaf(k1.z, S3, k1.x));
                    float t2v = fmaf(k2.y, C3, fmaf(k2.z, S3, k2.x));
                    float s = fmaf(t1v, Cb[px], fmaf(t2v, Sb[px], t0v));
                    accB[px] = (b == 0) ? s
                             : fmaf(s, (b == 1) ? Ct[px + 1] : St[px + 1], accB[px]);
                }
            }
            #pragma unroll
            for (int px = 0; px < 4; px++) {
                accA[px] = (a == 0) ? accB[px]
                         : fmaf(accB[px], (a == 1) ? Ct[px] : St[px], accA[px]);
            }
        }

        float* o = out + p * 16129 + h * 127 + w0;
        o[0] = accA[0]; o[1] = accA[1]; o[2] = accA[2];
        if (full) o[3] = accA[3];
    }
}

extern "C" void kernel_launch(void* const* d_in, const int* in_sizes, int n_in,
                              void* d_out, int out_size) {
    const float* x = (const float*)d_in[0];   // [32,3,128,128]
    const float* w = (const float*)d_in[1];   // [2,4,3]
    float* out = (float*)d_out;               // [32,3,127,127]

    const int nVirt  = 96 * 4096;             // padded strip space (shifts-only decode)
    const int blocks = 592;                   // persistent: 4 blocks/SM x 148 SMs
    qcl_fused_kernel<<<blocks, 256>>>(x, w, out, nVirt);
}

// round 11
// speedup vs baseline: 1.0411x; 1.0411x over previous
#include <cuda_runtime.h>

// K stored as 27 float4 entries {K[..,t3=0],K[..,t3=1],K[..,t3=2],0},
// plus flat copy layout for the main kernel's split-by-t3 view.
__device__ __align__(16) float g_Ks[3 * 27];   // [t3][t0*9+t1*3+t2]

// ---------------------------------------------------------------------------
// Setup kernel: ONE block, 256 threads. Parallel shuffle simulator for the
// 16x16 circuit unitary, M = Re(U^dag Z0 U), sparse 16-term projection to the
// 81 multilinear coefficients. ~1-2 us standalone.
// ---------------------------------------------------------------------------
__global__ void __launch_bounds__(256)
qcl_setup_kernel(const float* __restrict__ w) {
    __shared__ float sUr[16][17];
    __shared__ float sUi[16][17];
    __shared__ float sM[16][17];
    __shared__ float sgc[24], sgs[24];

    const int tid = threadIdx.x;

    if (tid < 24) {
        sgc[tid] = cosf(w[tid] * 0.5f);
        sgs[tid] = sinf(w[tid] * 0.5f);
    }
    __syncthreads();

    // shuffle simulator: thread owns amplitude kk of column col
    {
        const int lane = tid & 31;
        const int kk   = lane & 15;
        const int col  = ((tid >> 5) << 1) | (lane >> 4);

        float ar = (kk == col) ? 1.f : 0.f;
        float ai = 0.f;

        auto rot = [&](int m, float g00r, float g00i, float g01r, float g01i,
                              float g10r, float g10i, float g11r, float g11i) {
            float pr = __shfl_xor_sync(0xffffffffu, ar, m);
            float pi = __shfl_xor_sync(0xffffffffu, ai, m);
            bool  b  = (kk & m) != 0;
            float ur = b ? pr : ar, ui = b ? pi : ai;
            float wr = b ? ar : pr, wi = b ? ai : pi;
            float c0r = b ? g10r : g00r, c0i = b ? g10i : g00i;
            float c1r = b ? g11r : g01r, c1i = b ? g11i : g01i;
            ar = c0r * ur - c0i * ui + c1r * wr - c1i * wi;
            ai = c0r * ui + c0i * ur + c1r * wi + c1i * wr;
        };
        auto cnot = [&](int mc, int mt) {
            float pr = __shfl_xor_sync(0xffffffffu, ar, mt);
            float pi = __shfl_xor_sync(0xffffffffu, ai, mt);
            if (kk & mc) { ar = pr; ai = pi; }
        };

        #pragma unroll
        for (int g8 = 0; g8 < 8; g8++) {     // layer*4 + q
            int q = g8 & 3;
            int m = 8 >> q;
            int base = g8 * 3;
            float c, s;
            c = sgc[base + 0]; s = sgs[base + 0];          // RX: [[c,-is],[-is,c]]
            rot(m, c, 0.f, 0.f, -s, 0.f, -s, c, 0.f);
            c = sgc[base + 1]; s = sgs[base + 1];          // RY: [[c,-s],[s,c]]
            rot(m, c, 0.f, -s, 0.f, s, 0.f, c, 0.f);
            c = sgc[base + 2]; s = sgs[base + 2];          // RZ: diag(e^-it/2,e^it/2)
            rot(m, c, -s, 0.f, 0.f, 0.f, 0.f, c, s);
            if (q == 3) { cnot(8, 4); cnot(2, 1); cnot(8, 2); cnot(4, 1); }
        }

        sUr[kk][col] = ar;
        sUi[kk][col] = ai;
    }
    __syncthreads();

    // M[i][j] = Re(sum_k z_k conj(U[k][i]) U[k][j]), z_k = (k&8)?-1:+1
    {
        int i = tid >> 4, j = tid & 15;
        float acc = 0.f;
        #pragma unroll
        for (int k = 0; k < 16; k++) {
            float z = (k & 8) ? -1.f : 1.f;
            acc += z * (sUr[k][i] * sUr[k][j] + sUi[k][i] * sUi[k][j]);
        }
        sM[i][j] = acc;
    }
    __syncthreads();

    // sparse projection: K[t] = (1/16) sum_c (-1)^popc(c & smask) * M[c][c^xmask]
    if (tid < 81) {
        int t3 = tid % 3, r = tid / 3;
        int t2 = r % 3;  r /= 3;
        int t1 = r % 3;
        int t0 = r / 3;
        int xmask = ((t0 == 2) << 3) | ((t1 == 2) << 2) | ((t2 == 2) << 1) | (t3 == 2);
        int smask = ((t0 == 1) << 3) | ((t1 == 1) << 2) | ((t2 == 1) << 1) | (t3 == 1);
        float acc = 0.f;
        #pragma unroll
        for (int c = 0; c < 16; c++) {
            float sgn = (__popc(c & smask) & 1) ? -1.f : 1.f;
            acc += sgn * sM[c][c ^ xmask];
        }
        g_Ks[t3 * 27 + (t0 * 9 + t1 * 3 + t2)] = acc * 0.0625f;
    }
}

// ---------------------------------------------------------------------------
// Main kernel: R3 body verbatim (measured 12.8 us). One thread per 4-pixel
// strip; 5 top + 5 bottom sincos shared; contraction reads K via float4
// shared loads. Non-persistent indexed grid.
// ---------------------------------------------------------------------------
__global__ void __launch_bounds__(256)
qcl_main_kernel(const float* __restrict__ x, float* __restrict__ out, int nStrips) {
    __shared__ __align__(16) float sK[3 * 28];   // each 27-part padded to 28
    if (threadIdx.x < 84) {
        int part = threadIdx.x / 28, idx = threadIdx.x - part * 28;
        sK[threadIdx.x] = (idx < 27) ? g_Ks[part * 27 + idx] : 0.f;
    }
    __syncthreads();
    const float4* sK4 = (const float4*)sK;       // sK4[part*7 + v]

    int sid = blockIdx.x * blockDim.x + threadIdx.x;
    if (sid >= nStrips) return;

    // strips: 32 per row (last covers 3 pixels), 127 rows, 96 planes
    int p    = sid / 4064;            // 127*32
    int rem  = sid - p * 4064;
    int h    = rem >> 5;
    int w0   = (rem & 31) << 2;       // 0..124, 16B-aligned
    bool full = (w0 < 124);
    int npix  = full ? 4 : 3;

    const float* r0 = x + p * 16384 + h * 128 + w0;
    float4 t4 = *(const float4*)r0;
    float4 b4 = *(const float4*)(r0 + 128);
    float  t5 = full ? __ldg(r0 + 4)   : 0.f;
    float  b5 = full ? __ldg(r0 + 132) : 0.f;

    float Ct[5], St[5], Cb[5], Sb[5];
    __sincosf(t4.x, &St[0], &Ct[0]);  __sincosf(b4.x, &Sb[0], &Cb[0]);
    __sincosf(t4.y, &St[1], &Ct[1]);  __sincosf(b4.y, &Sb[1], &Cb[1]);
    __sincosf(t4.z, &St[2], &Ct[2]);  __sincosf(b4.z, &Sb[2], &Cb[2]);
    __sincosf(t4.w, &St[3], &Ct[3]);  __sincosf(b4.w, &Sb[3], &Cb[3]);
    __sincosf(t5,   &St[4], &Ct[4]);  __sincosf(b5,   &Sb[4], &Cb[4]);

    float* o = out + p * 16129 + h * 127 + w0;

    #pragma unroll
    for (int k = 0; k < 4; k++) {
        // wires: 0=top-left, 1=top-right, 2=bottom-left, 3=bottom-right
        float C0 = Ct[k],     S0 = St[k];
        float C1 = Ct[k + 1], S1 = St[k + 1];
        float C2 = Cb[k],     S2 = Sb[k];
        float C3 = Cb[k + 1], S3 = Sb[k + 1];

        // level t3: r[a] = K0[a] + K1[a]*C3 + K2[a]*S3, a = t0*9+t1*3+t2
        float r[28];
        #pragma unroll
        for (int v = 0; v < 7; v++) {
            float4 k0 = sK4[v], k1 = sK4[7 + v], k2 = sK4[14 + v];
            r[4 * v + 0] = fmaf(k1.x, C3, fmaf(k2.x, S3, k0.x));
            r[4 * v + 1] = fmaf(k1.y, C3, fmaf(k2.y, S3, k0.y));
            r[4 * v + 2] = fmaf(k1.z, C3, fmaf(k2.z, S3, k0.z));
            r[4 * v + 3] = fmaf(k1.w, C3, fmaf(k2.w, S3, k0.w));
        }

        // level t2
        float r2[9];
        #pragma unroll
        for (int a = 0; a < 9; a++)
            r2[a] = fmaf(r[3 * a + 1], C2, fmaf(r[3 * a + 2], S2, r[3 * a]));

        // levels t1, t0
        float ra = fmaf(r2[1], C1, fmaf(r2[2], S1, r2[0]));
        float rb = fmaf(r2[4], C1, fmaf(r2[5], S1, r2[3]));
        float rc = fmaf(r2[7], C1, fmaf(r2[8], S1, r2[6]));
        float ev = fmaf(rb, C0, fmaf(rc, S0, ra));

        if (k < npix) o[k] = ev;
    }
}

extern "C" void kernel_launch(void* const* d_in, const int* in_sizes, int n_in,
                              void* d_out, int out_size) {
    const float* x = (const float*)d_in[0];   // [32,3,128,128]
    const float* w = (const float*)d_in[1];   // [2,4,3]
    float* out = (float*)d_out;               // [32,3,127,127]

    qcl_setup_kernel<<<1, 256>>>(w);

    const int nStrips = 96 * 127 * 32;         // 390144
    const int blocks  = (nStrips + 255) / 256; // 1524
    qcl_main_kernel<<<blocks, 256>>>(x, out, nStrips);
}